// round 16
// baseline (speedup 1.0000x reference)
#include <cuda_runtime.h>
#include <cstdint>

#define NN      200000
#define EE      1200000
#define INDIM   128
#define HID     64
#define GG      1024
#define NCLS    6
#define LAYERS  3
#define BN_EPS  1e-5f
#define NBLK    ((NN + 1023) / 1024)   // 196 scan blocks

// ---------------- scratch (static device globals; no allocation) ----------------
__device__ float g_hA [(size_t)NN * HID];
__device__ float g_hB [(size_t)NN * HID];
__device__ float g_pool[GG * HID];
__device__ int   g_cnt [GG];
// CSR structures (rebuilt every launch; deterministic given inputs)
__device__ int   g_rowptr[NN + 1];
__device__ int   g_cursor[NN];
__device__ int   g_colidx[EE];
__device__ int   g_bsum[256];
__device__ int   g_boff[256];

// ---------------- packed f32x2 helpers (bit-exact dual fp32 FMA) ----------------
__device__ __forceinline__ unsigned long long ffma2(unsigned long long a,
                                                    unsigned long long b,
                                                    unsigned long long c) {
    unsigned long long d;
    asm("fma.rn.f32x2 %0, %1, %2, %3;" : "=l"(d) : "l"(a), "l"(b), "l"(c));
    return d;
}
__device__ __forceinline__ unsigned long long dup2(float w) {
    unsigned long long d;
    asm("mov.b64 %0, {%1, %1};" : "=l"(d) : "r"(__float_as_uint(w)));
    return d;
}
__device__ __forceinline__ void unpack2(unsigned long long v, float& lo, float& hi) {
    unsigned int a, b;
    asm("mov.b64 {%0, %1}, %2;" : "=r"(a), "=r"(b) : "l"(v));
    lo = __uint_as_float(a);
    hi = __uint_as_float(b);
}

// ================= CSR build =================
__global__ void csr_zero_kernel() {
    int i = blockIdx.x * blockDim.x + threadIdx.x;
    if (i < NN) g_cursor[i] = 0;
}

__global__ void csr_hist_kernel(const int* __restrict__ dst) {
    int e = blockIdx.x * blockDim.x + threadIdx.x;
    if (e < EE) atomicAdd(&g_cursor[__ldg(dst + e)], 1);
}

__global__ void csr_scan1_kernel() {
    __shared__ int wsum[8];
    int t = threadIdx.x, blk = blockIdx.x;
    int lane = t & 31, w = t >> 5;
    int base = blk * 1024 + t * 4;
    int c[4], s = 0;
#pragma unroll
    for (int k = 0; k < 4; k++) {
        c[k] = (base + k < NN) ? g_cursor[base + k] : 0;
        s += c[k];
    }
    int inc = s;
#pragma unroll
    for (int o = 1; o < 32; o <<= 1) {
        int n = __shfl_up_sync(0xffffffffu, inc, o);
        if (lane >= o) inc += n;
    }
    if (lane == 31) wsum[w] = inc;
    __syncthreads();
    if (t == 0) {
        int acc = 0;
#pragma unroll
        for (int i = 0; i < 8; i++) { int tmp = wsum[i]; wsum[i] = acc; acc += tmp; }
    }
    __syncthreads();
    int run = wsum[w] + inc - s;
#pragma unroll
    for (int k = 0; k < 4; k++) {
        if (base + k < NN) g_rowptr[base + k] = run;
        run += c[k];
    }
    if (t == 255) g_bsum[blk] = wsum[7] + inc;
}

__global__ void csr_scan2_kernel() {
    __shared__ int wsum[8];
    int t = threadIdx.x;
    int lane = t & 31, w = t >> 5;
    int v = (t < NBLK) ? g_bsum[t] : 0;
    int inc = v;
#pragma unroll
    for (int o = 1; o < 32; o <<= 1) {
        int n = __shfl_up_sync(0xffffffffu, inc, o);
        if (lane >= o) inc += n;
    }
    if (lane == 31) wsum[w] = inc;
    __syncthreads();
    if (t == 0) {
        int acc = 0;
#pragma unroll
        for (int i = 0; i < 8; i++) { int tmp = wsum[i]; wsum[i] = acc; acc += tmp; }
    }
    __syncthreads();
    if (t < NBLK) g_boff[t] = wsum[w] + inc - v;
}

__global__ void csr_scan3_kernel() {
    int i = blockIdx.x * blockDim.x + threadIdx.x;
    if (i < NN) {
        int r = g_rowptr[i] + g_boff[i >> 10];
        g_rowptr[i] = r;
        g_cursor[i] = r;
    }
    if (i == 0) g_rowptr[NN] = EE;
}

__global__ void csr_fill_kernel(const int* __restrict__ src,
                                const int* __restrict__ dst) {
    int e = blockIdx.x * blockDim.x + threadIdx.x;
    if (e >= EE) return;
    int d = __ldg(dst + e);
    int pos = atomicAdd(&g_cursor[d], 1);
    g_colidx[pos] = __ldg(src + e);
}

__global__ void zero_pool_kernel() {
    int i = blockIdx.x * blockDim.x + threadIdx.x;
    if (i < GG * HID) g_pool[i] = 0.f;
    if (i < GG)       g_cnt[i]  = 0;
}

// per-graph node counts (independent of layers)
__global__ void cnt_hist_kernel(const int* __restrict__ batch) {
    int i = blockIdx.x * blockDim.x + threadIdx.x;
    if (i < NN) atomicAdd(&g_cnt[__ldg(batch + i)], 1);
}

// ============================================================================
// GEMM micro-structure: tile 128 nodes x 64 outs, 256 threads, FFMA2 packed.
// ============================================================================
#define XPAD 132
#define SWZ(r, q) ((q) ^ ((r) & 7) ^ (((r) >> 3) & 7))

// ---------------- embed: full W resident in smem (staged once) ----------------
#define EMB_DYN ((32 * XPAD + 128 * 64) * 4)   // 49664 B -> 4 CTAs/SM

__global__ void __launch_bounds__(256, 4)
embed_kernel(const float* __restrict__ x,  const float* __restrict__ W,
             const float* __restrict__ bias,
             const float* __restrict__ bg, const float* __restrict__ bb,
             const float* __restrict__ bm, const float* __restrict__ bv,
             float* __restrict__ outh)
{
    extern __shared__ float esm[];
    float* xs   = esm;               // [32][XPAD]
    float* Wall = esm + 32 * XPAD;   // [128][64]

    const int t  = threadIdx.x;
    const int og = t & 15;
    const int ng = t >> 4;
    const int n0 = blockIdx.x * 128;

    // stage ALL of W once (coalesced float4; covered by first chunk's sync)
#pragma unroll
    for (int r = 0; r < 8; r++) {
        int i = r * 256 + t;
        reinterpret_cast<float4*>(Wall)[i] = reinterpret_cast<const float4*>(W)[i];
    }

    unsigned long long acc[4][4];
#pragma unroll
    for (int i = 0; i < 4; i++)
#pragma unroll
        for (int j = 0; j < 4; j++) acc[i][j] = 0ULL;

    for (int k0 = 0; k0 < INDIM; k0 += 32) {
#pragma unroll
        for (int r = 0; r < 4; r++) {
            int idx = r * 256 + t;
            int nn = idx >> 3, kq = idx & 7;
            int node = min(n0 + nn, NN - 1);
            float4 v = *reinterpret_cast<const float4*>(x + (size_t)node * INDIM + k0 + kq * 4);
            xs[(kq * 4 + 0) * XPAD + nn] = v.x; xs[(kq * 4 + 1) * XPAD + nn] = v.y;
            xs[(kq * 4 + 2) * XPAD + nn] = v.z; xs[(kq * 4 + 3) * XPAD + nn] = v.w;
        }
        __syncthreads();
#pragma unroll 8
        for (int kk = 0; kk < 32; kk++) {
            const ulonglong2* xp = reinterpret_cast<const ulonglong2*>(&xs[kk * XPAD + ng * 8]);
            ulonglong2 xA = xp[0], xB = xp[1];
            unsigned long long xv[4] = {xA.x, xA.y, xB.x, xB.y};
            float4 wf = *reinterpret_cast<const float4*>(&Wall[(k0 + kk) * 64 + og * 4]);
            unsigned long long wv[4] = {dup2(wf.x), dup2(wf.y), dup2(wf.z), dup2(wf.w)};
#pragma unroll
            for (int i = 0; i < 4; i++)
#pragma unroll
                for (int j = 0; j < 4; j++) acc[i][j] = ffma2(xv[i], wv[j], acc[i][j]);
        }
        __syncthreads();
    }

    float s[4], sh[4];
#pragma unroll
    for (int j = 0; j < 4; j++) {
        int o = og * 4 + j;
        s[j]  = __ldg(bg + o) * rsqrtf(__ldg(bv + o) + BN_EPS);
        sh[j] = (__ldg(bias + o) - __ldg(bm + o)) * s[j] + __ldg(bb + o);
    }
#pragma unroll
    for (int i = 0; i < 4; i++) {
        float f0[4], f1[4];
#pragma unroll
        for (int j = 0; j < 4; j++) unpack2(acc[i][j], f0[j], f1[j]);
        int node0 = n0 + ng * 8 + 2 * i;
        if (node0 < NN) {
            float4 v;
            v.x = fmaxf(f0[0] * s[0] + sh[0], 0.f);
            v.y = fmaxf(f0[1] * s[1] + sh[1], 0.f);
            v.z = fmaxf(f0[2] * s[2] + sh[2], 0.f);
            v.w = fmaxf(f0[3] * s[3] + sh[3], 0.f);
            *reinterpret_cast<float4*>(outh + (size_t)node0 * HID + og * 4) = v;
        }
        if (node0 + 1 < NN) {
            float4 v;
            v.x = fmaxf(f1[0] * s[0] + sh[0], 0.f);
            v.y = fmaxf(f1[1] * s[1] + sh[1], 0.f);
            v.z = fmaxf(f1[2] * s[2] + sh[2], 0.f);
            v.w = fmaxf(f1[3] * s[3] + sh[3], 0.f);
            *reinterpret_cast<float4*>(outh + (size_t)(node0 + 1) * HID + og * 4) = v;
        }
    }
}

// ============================================================================
// fused gather + GIN MLP — EXACT R11 winner. W2 aliases W1's smem slab;
// 4 CTAs/SM. Gather: (node, 32B chunk-pair), edge-batch 4 -> 8 loads in
// flight. FINAL=true: epilogue2 red.adds straight into g_pool.
// ============================================================================
#define MLP_DYN ((8448 + 4096) * 4)

template<bool FINAL>
__global__ void __launch_bounds__(256, 4)
fused_mlp(const float* __restrict__ inh,
          const float* __restrict__ W1, const float* __restrict__ b1,
          const float* __restrict__ g1, const float* __restrict__ bb1,
          const float* __restrict__ m1, const float* __restrict__ v1,
          const float* __restrict__ W2, const float* __restrict__ b2,
          const float* __restrict__ g2, const float* __restrict__ bb2,
          const float* __restrict__ m2, const float* __restrict__ v2,
          float* __restrict__ outh, const int* __restrict__ batch)
{
    extern __shared__ float sm[];
    float* asz = sm;                 // [64][132], swizzled chunks (agg, then z)
    float* Wsm = sm + 8448;          // [64][64]  (W1, then W2)

    const int t  = threadIdx.x;
    const int og = t & 15;
    const int ng = t >> 4;
    const int n0 = blockIdx.x * 128;

    // ---------- stage W1 (coalesced float4) ----------
#pragma unroll
    for (int r = 0; r < 4; r++) {
        int i = r * 256 + t;
        reinterpret_cast<float4*>(Wsm)[i] = reinterpret_cast<const float4*>(W1)[i];
    }

    // ---------- gather: asz[k][node] = inh[node][k] + sum_nbrs inh[src][k] ----------
#pragma unroll
    for (int r = 0; r < 4; r++) {
        int idx  = r * 256 + t;
        int node = idx >> 3;
        int cp   = idx & 7;
        int gn   = n0 + node;
        float4 a0 = make_float4(0.f, 0.f, 0.f, 0.f);
        float4 a1 = a0;
        if (gn < NN) {
            const float* rp = inh + (size_t)gn * HID + cp * 8;
            a0 = *reinterpret_cast<const float4*>(rp);
            a1 = *reinterpret_cast<const float4*>(rp + 4);
            int beg = __ldg(&g_rowptr[gn]);
            int end = __ldg(&g_rowptr[gn + 1]);
            int e = beg;
            for (; e + 4 <= end; e += 4) {      // 4 edges x 2 chunks = 8 loads in flight
                int s0 = __ldg(&g_colidx[e]);
                int s1 = __ldg(&g_colidx[e + 1]);
                int s2 = __ldg(&g_colidx[e + 2]);
                int s3 = __ldg(&g_colidx[e + 3]);
                const float* p0 = inh + (size_t)s0 * HID + cp * 8;
                const float* p1 = inh + (size_t)s1 * HID + cp * 8;
                const float* p2 = inh + (size_t)s2 * HID + cp * 8;
                const float* p3 = inh + (size_t)s3 * HID + cp * 8;
                float4 u00 = *reinterpret_cast<const float4*>(p0);
                float4 u01 = *reinterpret_cast<const float4*>(p0 + 4);
                float4 u10 = *reinterpret_cast<const float4*>(p1);
                float4 u11 = *reinterpret_cast<const float4*>(p1 + 4);
                float4 u20 = *reinterpret_cast<const float4*>(p2);
                float4 u21 = *reinterpret_cast<const float4*>(p2 + 4);
                float4 u30 = *reinterpret_cast<const float4*>(p3);
                float4 u31 = *reinterpret_cast<const float4*>(p3 + 4);
                a0.x += u00.x; a0.y += u00.y; a0.z += u00.z; a0.w += u00.w;
                a1.x += u01.x; a1.y += u01.y; a1.z += u01.z; a1.w += u01.w;
                a0.x += u10.x; a0.y += u10.y; a0.z += u10.z; a0.w += u10.w;
                a1.x += u11.x; a1.y += u11.y; a1.z += u11.z; a1.w += u11.w;
                a0.x += u20.x; a0.y += u20.y; a0.z += u20.z; a0.w += u20.w;
                a1.x += u21.x; a1.y += u21.y; a1.z += u21.z; a1.w += u21.w;
                a0.x += u30.x; a0.y += u30.y; a0.z += u30.z; a0.w += u30.w;
                a1.x += u31.x; a1.y += u31.y; a1.z += u31.z; a1.w += u31.w;
            }
            for (; e < end; e++) {
                int s = __ldg(&g_colidx[e]);
                const float* p = inh + (size_t)s * HID + cp * 8;
                float4 u0 = *reinterpret_cast<const float4*>(p);
                float4 u1 = *reinterpret_cast<const float4*>(p + 4);
                a0.x += u0.x; a0.y += u0.y; a0.z += u0.z; a0.w += u0.w;
                a1.x += u1.x; a1.y += u1.y; a1.z += u1.z; a1.w += u1.w;
            }
        }
        int q = node >> 2, lo = node & 3;
        float v0[4] = {a0.x, a0.y, a0.z, a0.w};
        float v1[4] = {a1.x, a1.y, a1.z, a1.w};
#pragma unroll
        for (int j = 0; j < 4; j++) {
            int row0 = cp * 8 + j;
            int row1 = cp * 8 + 4 + j;
            asz[row0 * XPAD + SWZ(row0, q) * 4 + lo] = v0[j];
            asz[row1 * XPAD + SWZ(row1, q) * 4 + lo] = v1[j];
        }
    }
    __syncthreads();

    unsigned long long acc[4][4];
#pragma unroll
    for (int i = 0; i < 4; i++)
#pragma unroll
        for (int j = 0; j < 4; j++) acc[i][j] = 0ULL;

    // ---------- GEMM1 (reads W1 from Wsm) ----------
#pragma unroll 8
    for (int kk = 0; kk < 64; kk++) {
        int p0 = SWZ(kk, 2 * ng);
        int p1 = SWZ(kk, 2 * ng + 1);
        float4 xa4 = *reinterpret_cast<const float4*>(&asz[kk * XPAD + p0 * 4]);
        float4 xb4 = *reinterpret_cast<const float4*>(&asz[kk * XPAD + p1 * 4]);
        const ulonglong2* pa = reinterpret_cast<const ulonglong2*>(&xa4);
        const ulonglong2* pb = reinterpret_cast<const ulonglong2*>(&xb4);
        unsigned long long xv[4] = {pa->x, pa->y, pb->x, pb->y};
        float4 wf = *reinterpret_cast<const float4*>(&Wsm[kk * 64 + og * 4]);
        unsigned long long wv[4] = {dup2(wf.x), dup2(wf.y), dup2(wf.z), dup2(wf.w)};
#pragma unroll
        for (int i = 0; i < 4; i++)
#pragma unroll
            for (int j = 0; j < 4; j++) acc[i][j] = ffma2(xv[i], wv[j], acc[i][j]);
    }
    __syncthreads();   // W1 reads and asz reads complete

    // ---------- stage W2 over W1's slab (safe post-sync; ready at next sync) ----
#pragma unroll
    for (int r = 0; r < 4; r++) {
        int i = r * 256 + t;
        reinterpret_cast<float4*>(Wsm)[i] = reinterpret_cast<const float4*>(W2)[i];
    }

    // ---------- epilogue1: BN + relu -> asz (as z) ----------
    {
        float s[4], sh[4];
#pragma unroll
        for (int j = 0; j < 4; j++) {
            int o = og * 4 + j;
            s[j]  = __ldg(g1 + o) * rsqrtf(__ldg(v1 + o) + BN_EPS);
            sh[j] = (__ldg(b1 + o) - __ldg(m1 + o)) * s[j] + __ldg(bb1 + o);
        }
        float f0[4][4], f1[4][4];
#pragma unroll
        for (int i = 0; i < 4; i++)
#pragma unroll
            for (int j = 0; j < 4; j++) unpack2(acc[i][j], f0[i][j], f1[i][j]);
#pragma unroll
        for (int j = 0; j < 4; j++) {
            int row = og * 4 + j;
            float4 A, B;
            A.x = fmaxf(f0[0][j] * s[j] + sh[j], 0.f);
            A.y = fmaxf(f1[0][j] * s[j] + sh[j], 0.f);
            A.z = fmaxf(f0[1][j] * s[j] + sh[j], 0.f);
            A.w = fmaxf(f1[1][j] * s[j] + sh[j], 0.f);
            B.x = fmaxf(f0[2][j] * s[j] + sh[j], 0.f);
            B.y = fmaxf(f1[2][j] * s[j] + sh[j], 0.f);
            B.z = fmaxf(f0[3][j] * s[j] + sh[j], 0.f);
            B.w = fmaxf(f1[3][j] * s[j] + sh[j], 0.f);
            *reinterpret_cast<float4*>(&asz[row * XPAD + SWZ(row, 2 * ng) * 4])     = A;
            *reinterpret_cast<float4*>(&asz[row * XPAD + SWZ(row, 2 * ng + 1) * 4]) = B;
        }
    }
    __syncthreads();   // z ready AND W2 staged

    // ---------- GEMM2 (reads W2 from Wsm) ----------
#pragma unroll
    for (int i = 0; i < 4; i++)
#pragma unroll
        for (int j = 0; j < 4; j++) acc[i][j] = 0ULL;

#pragma unroll 8
    for (int kk = 0; kk < 64; kk++) {
        int p0 = SWZ(kk, 2 * ng);
        int p1 = SWZ(kk, 2 * ng + 1);
        float4 xa4 = *reinterpret_cast<const float4*>(&asz[kk * XPAD + p0 * 4]);
        float4 xb4 = *reinterpret_cast<const float4*>(&asz[kk * XPAD + p1 * 4]);
        const ulonglong2* pa = reinterpret_cast<const ulonglong2*>(&xa4);
        const ulonglong2* pb = reinterpret_cast<const ulonglong2*>(&xb4);
        unsigned long long xv[4] = {pa->x, pa->y, pb->x, pb->y};
        float4 wf = *reinterpret_cast<const float4*>(&Wsm[kk * 64 + og * 4]);
        unsigned long long wv[4] = {dup2(wf.x), dup2(wf.y), dup2(wf.z), dup2(wf.w)};
#pragma unroll
        for (int i = 0; i < 4; i++)
#pragma unroll
            for (int j = 0; j < 4; j++) acc[i][j] = ffma2(xv[i], wv[j], acc[i][j]);
    }

    // ---------- epilogue2: BN + relu -> global h, or pool reduction ----------
    float s[4], sh[4];
#pragma unroll
    for (int j = 0; j < 4; j++) {
        int o = og * 4 + j;
        s[j]  = __ldg(g2 + o) * rsqrtf(__ldg(v2 + o) + BN_EPS);
        sh[j] = (__ldg(b2 + o) - __ldg(m2 + o)) * s[j] + __ldg(bb2 + o);
    }
#pragma unroll
    for (int i = 0; i < 4; i++) {
        float f0[4], f1[4];
#pragma unroll
        for (int j = 0; j < 4; j++) unpack2(acc[i][j], f0[j], f1[j]);
        int node0 = n0 + ng * 8 + 2 * i;
        if (node0 < NN) {
            float4 v;
            v.x = fmaxf(f0[0] * s[0] + sh[0], 0.f);
            v.y = fmaxf(f0[1] * s[1] + sh[1], 0.f);
            v.z = fmaxf(f0[2] * s[2] + sh[2], 0.f);
            v.w = fmaxf(f0[3] * s[3] + sh[3], 0.f);
            if (FINAL) {
                int b = __ldg(batch + node0);
                float4* p = reinterpret_cast<float4*>(g_pool + b * HID + og * 4);
                asm volatile("red.global.add.v4.f32 [%0], {%1,%2,%3,%4};"
                             :: "l"(p), "f"(v.x), "f"(v.y), "f"(v.z), "f"(v.w) : "memory");
            } else {
                *reinterpret_cast<float4*>(outh + (size_t)node0 * HID + og * 4) = v;
            }
        }
        if (node0 + 1 < NN) {
            float4 v;
            v.x = fmaxf(f1[0] * s[0] + sh[0], 0.f);
            v.y = fmaxf(f1[1] * s[1] + sh[1], 0.f);
            v.z = fmaxf(f1[2] * s[2] + sh[2], 0.f);
            v.w = fmaxf(f1[3] * s[3] + sh[3], 0.f);
            if (FINAL) {
                int b = __ldg(batch + node0 + 1);
                float4* p = reinterpret_cast<float4*>(g_pool + b * HID + og * 4);
                asm volatile("red.global.add.v4.f32 [%0], {%1,%2,%3,%4};"
                             :: "l"(p), "f"(v.x), "f"(v.y), "f"(v.z), "f"(v.w) : "memory");
            } else {
                *reinterpret_cast<float4*>(outh + (size_t)(node0 + 1) * HID + og * 4) = v;
            }
        }
    }
}

// ---------------- classifier head ----------------
__global__ void classifier_kernel(const float* __restrict__ W1, const float* __restrict__ b1,
                                  const float* __restrict__ W2, const float* __restrict__ b2,
                                  float* __restrict__ out)
{
    __shared__ float W1s[64 * 32];
    __shared__ float W2s[32 * NCLS];
    __shared__ float b1s[32];
    __shared__ float b2s[NCLS];
    int t = threadIdx.x;
    for (int i = t; i < 64 * 32;   i += 256) W1s[i] = W1[i];
    for (int i = t; i < 32 * NCLS; i += 256) W2s[i] = W2[i];
    if (t < 32)   b1s[t] = b1[t];
    if (t < NCLS) b2s[t] = b2[t];
    __syncthreads();

    int g = blockIdx.x * 256 + t;
    if (g >= GG) return;
    float inv = 1.f / fmaxf((float)g_cnt[g], 1.f);

    float h1[32];
#pragma unroll
    for (int j = 0; j < 32; j++) h1[j] = b1s[j];
    for (int k = 0; k < HID; k++) {
        float p = g_pool[g * HID + k] * inv;
#pragma unroll
        for (int j = 0; j < 32; j++) h1[j] += p * W1s[k * 32 + j];
    }
#pragma unroll
    for (int j = 0; j < 32; j++) h1[j] = fmaxf(h1[j], 0.f);

#pragma unroll
    for (int c = 0; c < NCLS; c++) {
        float o = b2s[c];
#pragma unroll
        for (int j = 0; j < 32; j++) o += h1[j] * W2s[j * NCLS + c];
        out[g * NCLS + c] = o;
    }
}

// ---------------- launcher ----------------
extern "C" void kernel_launch(void* const* d_in, const int* in_sizes, int n_in,
                              void* d_out, int out_size)
{
    const float* x      = (const float*)d_in[0];
    const int*   ei     = (const int*)  d_in[1];
    const int*   batch  = (const int*)  d_in[2];
    const float* emb_w  = (const float*)d_in[3];
    const float* emb_b  = (const float*)d_in[4];
    const float* ibn_g  = (const float*)d_in[5];
    const float* ibn_b  = (const float*)d_in[6];
    const float* ibn_m  = (const float*)d_in[7];
    const float* ibn_v  = (const float*)d_in[8];
    const float* fc1_w  = (const float*)d_in[9];
    const float* fc1_b  = (const float*)d_in[10];
    const float* mbn_g  = (const float*)d_in[11];
    const float* mbn_b  = (const float*)d_in[12];
    const float* mbn_m  = (const float*)d_in[13];
    const float* mbn_v  = (const float*)d_in[14];
    const float* fc2_w  = (const float*)d_in[15];
    const float* fc2_b  = (const float*)d_in[16];
    const float* obn_g  = (const float*)d_in[17];
    const float* obn_b  = (const float*)d_in[18];
    const float* obn_m  = (const float*)d_in[19];
    const float* obn_v  = (const float*)d_in[20];
    const float* cls1_w = (const float*)d_in[21];
    const float* cls1_b = (const float*)d_in[22];
    const float* cls2_w = (const float*)d_in[23];
    const float* cls2_b = (const float*)d_in[24];
    float* out = (float*)d_out;

    const int* src = ei;        // edge_index[0]
    const int* dst = ei + EE;   // edge_index[1]

    float *hA, *hB;
    cudaGetSymbolAddress((void**)&hA, g_hA);
    cudaGetSymbolAddress((void**)&hB, g_hB);

    cudaFuncSetAttribute(embed_kernel,     cudaFuncAttributeMaxDynamicSharedMemorySize, EMB_DYN);
    cudaFuncSetAttribute(fused_mlp<false>, cudaFuncAttributeMaxDynamicSharedMemorySize, MLP_DYN);
    cudaFuncSetAttribute(fused_mlp<true>,  cudaFuncAttributeMaxDynamicSharedMemorySize, MLP_DYN);

    const int NB = (NN + 127) / 128;

    // Side stream forked off the capture line via events.
    cudaStream_t s2;
    cudaEvent_t evF, evJ;
    cudaStreamCreateWithFlags(&s2, cudaStreamNonBlocking);
    cudaEventCreateWithFlags(&evF, cudaEventDisableTiming);
    cudaEventCreateWithFlags(&evJ, cudaEventDisableTiming);

    cudaEventRecord(evF, 0);
    cudaStreamWaitEvent(s2, evF, 0);

    // ---- side stream: CSR build + pool/cnt init (independent of embed) ----
    csr_zero_kernel <<<(NN + 255) / 256, 256, 0, s2>>>();
    csr_hist_kernel <<<(EE + 255) / 256, 256, 0, s2>>>(dst);
    csr_scan1_kernel<<<NBLK, 256, 0, s2>>>();
    csr_scan2_kernel<<<1, 256, 0, s2>>>();
    csr_scan3_kernel<<<(NN + 255) / 256, 256, 0, s2>>>();
    csr_fill_kernel <<<(EE + 255) / 256, 256, 0, s2>>>(src, dst);
    zero_pool_kernel<<<(GG * HID + 255) / 256, 256, 0, s2>>>();
    cnt_hist_kernel <<<(NN + 255) / 256, 256, 0, s2>>>(batch);
    cudaEventRecord(evJ, s2);

    // ---- main stream: embed runs concurrently with the side branch ----
    embed_kernel<<<NB, 256, EMB_DYN>>>(x, emb_w, emb_b, ibn_g, ibn_b, ibn_m, ibn_v, hA);

    cudaStreamWaitEvent(0, evJ, 0);   // join: CSR + pool init done

    // ping-pong layers; final layer reduces straight into g_pool
    float* bufs[2] = {hA, hB};
    for (int l = 0; l < LAYERS; l++) {
        const float* inp  = bufs[l & 1];
        float*       outp = bufs[(l + 1) & 1];
        if (l < LAYERS - 1) {
            fused_mlp<false><<<NB, 256, MLP_DYN>>>(
                inp,
                fc1_w + (size_t)l * HID * HID, fc1_b + l * HID,
                mbn_g + l * HID, mbn_b + l * HID, mbn_m + l * HID, mbn_v + l * HID,
                fc2_w + (size_t)l * HID * HID, fc2_b + l * HID,
                obn_g + l * HID, obn_b + l * HID, obn_m + l * HID, obn_v + l * HID,
                outp, batch);
        } else {
            fused_mlp<true><<<NB, 256, MLP_DYN>>>(
                inp,
                fc1_w + (size_t)l * HID * HID, fc1_b + l * HID,
                mbn_g + l * HID, mbn_b + l * HID, mbn_m + l * HID, mbn_v + l * HID,
                fc2_w + (size_t)l * HID * HID, fc2_b + l * HID,
                obn_g + l * HID, obn_b + l * HID, obn_m + l * HID, obn_v + l * HID,
                outp, batch);
        }
    }

    classifier_kernel<<<(GG + 255) / 256, 256>>>(cls1_w, cls1_b, cls2_w, cls2_b, out);
}

// round 17
// speedup vs baseline: 1.0185x; 1.0185x over previous
#include <cuda_runtime.h>
#include <cstdint>

#define NN      200000
#define EE      1200000
#define INDIM   128
#define HID     64
#define GG      1024
#define NCLS    6
#define LAYERS  3
#define BN_EPS  1e-5f
#define NBLK    ((NN + 1023) / 1024)   // 196 scan blocks

// ---------------- scratch (static device globals; no allocation) ----------------
__device__ float g_hA [(size_t)NN * HID];
__device__ float g_hB [(size_t)NN * HID];
__device__ float g_pool[GG * HID];
__device__ int   g_cnt [GG];
// CSR structures (rebuilt every launch; deterministic given inputs)
__device__ int   g_rowptr[NN + 1];
__device__ int   g_cursor[NN];
__device__ int   g_colidx[EE];
__device__ int   g_bsum[256];
__device__ int   g_boff[256];

// ---------------- packed f32x2 helpers (bit-exact dual fp32 FMA) ----------------
__device__ __forceinline__ unsigned long long ffma2(unsigned long long a,
                                                    unsigned long long b,
                                                    unsigned long long c) {
    unsigned long long d;
    asm("fma.rn.f32x2 %0, %1, %2, %3;" : "=l"(d) : "l"(a), "l"(b), "l"(c));
    return d;
}
__device__ __forceinline__ unsigned long long dup2(float w) {
    unsigned long long d;
    asm("mov.b64 %0, {%1, %1};" : "=l"(d) : "r"(__float_as_uint(w)));
    return d;
}
__device__ __forceinline__ void unpack2(unsigned long long v, float& lo, float& hi) {
    unsigned int a, b;
    asm("mov.b64 {%0, %1}, %2;" : "=r"(a), "=r"(b) : "l"(v));
    lo = __uint_as_float(a);
    hi = __uint_as_float(b);
}

// ================= CSR build =================
__global__ void csr_zero_kernel() {
    int i = blockIdx.x * blockDim.x + threadIdx.x;
    if (i < NN) g_cursor[i] = 0;
}

__global__ void csr_hist_kernel(const int* __restrict__ dst) {
    int e = blockIdx.x * blockDim.x + threadIdx.x;
    if (e < EE) atomicAdd(&g_cursor[__ldg(dst + e)], 1);
}

__global__ void csr_scan1_kernel() {
    __shared__ int wsum[8];
    int t = threadIdx.x, blk = blockIdx.x;
    int lane = t & 31, w = t >> 5;
    int base = blk * 1024 + t * 4;
    int c[4], s = 0;
#pragma unroll
    for (int k = 0; k < 4; k++) {
        c[k] = (base + k < NN) ? g_cursor[base + k] : 0;
        s += c[k];
    }
    int inc = s;
#pragma unroll
    for (int o = 1; o < 32; o <<= 1) {
        int n = __shfl_up_sync(0xffffffffu, inc, o);
        if (lane >= o) inc += n;
    }
    if (lane == 31) wsum[w] = inc;
    __syncthreads();
    if (t == 0) {
        int acc = 0;
#pragma unroll
        for (int i = 0; i < 8; i++) { int tmp = wsum[i]; wsum[i] = acc; acc += tmp; }
    }
    __syncthreads();
    int run = wsum[w] + inc - s;
#pragma unroll
    for (int k = 0; k < 4; k++) {
        if (base + k < NN) g_rowptr[base + k] = run;
        run += c[k];
    }
    if (t == 255) g_bsum[blk] = wsum[7] + inc;
}

__global__ void csr_scan2_kernel() {
    __shared__ int wsum[8];
    int t = threadIdx.x;
    int lane = t & 31, w = t >> 5;
    int v = (t < NBLK) ? g_bsum[t] : 0;
    int inc = v;
#pragma unroll
    for (int o = 1; o < 32; o <<= 1) {
        int n = __shfl_up_sync(0xffffffffu, inc, o);
        if (lane >= o) inc += n;
    }
    if (lane == 31) wsum[w] = inc;
    __syncthreads();
    if (t == 0) {
        int acc = 0;
#pragma unroll
        for (int i = 0; i < 8; i++) { int tmp = wsum[i]; wsum[i] = acc; acc += tmp; }
    }
    __syncthreads();
    if (t < NBLK) g_boff[t] = wsum[w] + inc - v;
}

__global__ void csr_scan3_kernel() {
    int i = blockIdx.x * blockDim.x + threadIdx.x;
    if (i < NN) {
        int r = g_rowptr[i] + g_boff[i >> 10];
        g_rowptr[i] = r;
        g_cursor[i] = r;
    }
    if (i == 0) g_rowptr[NN] = EE;
}

__global__ void csr_fill_kernel(const int* __restrict__ src,
                                const int* __restrict__ dst) {
    int e = blockIdx.x * blockDim.x + threadIdx.x;
    if (e >= EE) return;
    int d = __ldg(dst + e);
    int pos = atomicAdd(&g_cursor[d], 1);
    g_colidx[pos] = __ldg(src + e);
}

__global__ void zero_pool_kernel() {
    int i = blockIdx.x * blockDim.x + threadIdx.x;
    if (i < GG * HID) g_pool[i] = 0.f;
    if (i < GG)       g_cnt[i]  = 0;
}

// per-graph node counts (independent of layers)
__global__ void cnt_hist_kernel(const int* __restrict__ batch) {
    int i = blockIdx.x * blockDim.x + threadIdx.x;
    if (i < NN) atomicAdd(&g_cnt[__ldg(batch + i)], 1);
}

// ============================================================================
// GEMM micro-structure: tile 128 nodes x 64 outs, 256 threads, FFMA2 packed.
// ============================================================================
#define XPAD 132
#define SWZ(r, q) ((q) ^ ((r) & 7) ^ (((r) >> 3) & 7))

__global__ void __launch_bounds__(256, 4)
embed_kernel(const float* __restrict__ x,  const float* __restrict__ W,
             const float* __restrict__ bias,
             const float* __restrict__ bg, const float* __restrict__ bb,
             const float* __restrict__ bm, const float* __restrict__ bv,
             float* __restrict__ outh)
{
    __shared__ float xs[32][XPAD];
    __shared__ float Wsm[32][64];

    const int t  = threadIdx.x;
    const int og = t & 15;
    const int ng = t >> 4;
    const int n0 = blockIdx.x * 128;

    unsigned long long acc[4][4];
#pragma unroll
    for (int i = 0; i < 4; i++)
#pragma unroll
        for (int j = 0; j < 4; j++) acc[i][j] = 0ULL;

    for (int k0 = 0; k0 < INDIM; k0 += 32) {
#pragma unroll
        for (int r = 0; r < 4; r++) {
            int idx = r * 256 + t;
            int nn = idx >> 3, kq = idx & 7;
            int node = min(n0 + nn, NN - 1);
            float4 v = *reinterpret_cast<const float4*>(x + (size_t)node * INDIM + k0 + kq * 4);
            xs[kq * 4 + 0][nn] = v.x; xs[kq * 4 + 1][nn] = v.y;
            xs[kq * 4 + 2][nn] = v.z; xs[kq * 4 + 3][nn] = v.w;
        }
#pragma unroll
        for (int r = 0; r < 8; r++) {
            int i = r * 256 + t;
            int kk = i >> 6, oo = i & 63;
            Wsm[kk][oo] = W[(size_t)(k0 + kk) * HID + oo];
        }
        __syncthreads();
#pragma unroll 8
        for (int kk = 0; kk < 32; kk++) {
            const ulonglong2* xp = reinterpret_cast<const ulonglong2*>(&xs[kk][ng * 8]);
            ulonglong2 xA = xp[0], xB = xp[1];
            unsigned long long xv[4] = {xA.x, xA.y, xB.x, xB.y};
            float4 wf = *reinterpret_cast<const float4*>(&Wsm[kk][og * 4]);
            unsigned long long wv[4] = {dup2(wf.x), dup2(wf.y), dup2(wf.z), dup2(wf.w)};
#pragma unroll
            for (int i = 0; i < 4; i++)
#pragma unroll
                for (int j = 0; j < 4; j++) acc[i][j] = ffma2(xv[i], wv[j], acc[i][j]);
        }
        __syncthreads();
    }

    float s[4], sh[4];
#pragma unroll
    for (int j = 0; j < 4; j++) {
        int o = og * 4 + j;
        s[j]  = __ldg(bg + o) * rsqrtf(__ldg(bv + o) + BN_EPS);
        sh[j] = (__ldg(bias + o) - __ldg(bm + o)) * s[j] + __ldg(bb + o);
    }
#pragma unroll
    for (int i = 0; i < 4; i++) {
        float f0[4], f1[4];
#pragma unroll
        for (int j = 0; j < 4; j++) unpack2(acc[i][j], f0[j], f1[j]);
        int node0 = n0 + ng * 8 + 2 * i;
        if (node0 < NN) {
            float4 v;
            v.x = fmaxf(f0[0] * s[0] + sh[0], 0.f);
            v.y = fmaxf(f0[1] * s[1] + sh[1], 0.f);
            v.z = fmaxf(f0[2] * s[2] + sh[2], 0.f);
            v.w = fmaxf(f0[3] * s[3] + sh[3], 0.f);
            *reinterpret_cast<float4*>(outh + (size_t)node0 * HID + og * 4) = v;
        }
        if (node0 + 1 < NN) {
            float4 v;
            v.x = fmaxf(f1[0] * s[0] + sh[0], 0.f);
            v.y = fmaxf(f1[1] * s[1] + sh[1], 0.f);
            v.z = fmaxf(f1[2] * s[2] + sh[2], 0.f);
            v.w = fmaxf(f1[3] * s[3] + sh[3], 0.f);
            *reinterpret_cast<float4*>(outh + (size_t)(node0 + 1) * HID + og * 4) = v;
        }
    }
}

// ============================================================================
// fused gather + GIN MLP. W2 aliases W1's smem slab; 4 blocks/SM.
// Gather: 8 threads/node (32B chunk-pairs), edge-batch 4 -> 8 loads in flight.
// FINAL=true: epilogue2 red.adds straight into g_pool.
// ============================================================================
#define MLP_DYN ((8448 + 4096) * 4)

template<bool FINAL>
__global__ void __launch_bounds__(256, 4)
fused_mlp(const float* __restrict__ inh,
          const float* __restrict__ W1, const float* __restrict__ b1,
          const float* __restrict__ g1, const float* __restrict__ bb1,
          const float* __restrict__ m1, const float* __restrict__ v1,
          const float* __restrict__ W2, const float* __restrict__ b2,
          const float* __restrict__ g2, const float* __restrict__ bb2,
          const float* __restrict__ m2, const float* __restrict__ v2,
          float* __restrict__ outh, const int* __restrict__ batch)
{
    extern __shared__ float sm[];
    float* asz = sm;                 // [64][132], swizzled chunks (agg, then z)
    float* Wsm = sm + 8448;          // [64][64]  (W1, then W2)

    const int t  = threadIdx.x;
    const int og = t & 15;
    const int ng = t >> 4;
    const int n0 = blockIdx.x * 128;

    // ---------- stage W1 (coalesced float4) ----------
#pragma unroll
    for (int r = 0; r < 4; r++) {
        int i = r * 256 + t;
        reinterpret_cast<float4*>(Wsm)[i] = reinterpret_cast<const float4*>(W1)[i];
    }

    // ---------- gather: asz[k][node] = inh[node][k] + sum_nbrs inh[src][k] ----------
    // item = (node, 32B chunk-pair); 128 nodes x 8 pairs = 1024 items, 4 per thread
#pragma unroll
    for (int r = 0; r < 4; r++) {
        int idx  = r * 256 + t;
        int node = idx >> 3;        // 0..127
        int cp   = idx & 7;         // chunk pair -> chunks 2cp, 2cp+1
        int gn   = n0 + node;
        float4 a0 = make_float4(0.f, 0.f, 0.f, 0.f);
        float4 a1 = a0;
        if (gn < NN) {
            const float* rp = inh + (size_t)gn * HID + cp * 8;
            a0 = *reinterpret_cast<const float4*>(rp);
            a1 = *reinterpret_cast<const float4*>(rp + 4);
            int beg = __ldg(&g_rowptr[gn]);
            int end = __ldg(&g_rowptr[gn + 1]);
            int e = beg;
            for (; e + 4 <= end; e += 4) {      // 4 edges x 2 chunks = 8 loads in flight
                int s0 = __ldg(&g_colidx[e]);
                int s1 = __ldg(&g_colidx[e + 1]);
                int s2 = __ldg(&g_colidx[e + 2]);
                int s3 = __ldg(&g_colidx[e + 3]);
                const float* p0 = inh + (size_t)s0 * HID + cp * 8;
                const float* p1 = inh + (size_t)s1 * HID + cp * 8;
                const float* p2 = inh + (size_t)s2 * HID + cp * 8;
                const float* p3 = inh + (size_t)s3 * HID + cp * 8;
                float4 u00 = *reinterpret_cast<const float4*>(p0);
                float4 u01 = *reinterpret_cast<const float4*>(p0 + 4);
                float4 u10 = *reinterpret_cast<const float4*>(p1);
                float4 u11 = *reinterpret_cast<const float4*>(p1 + 4);
                float4 u20 = *reinterpret_cast<const float4*>(p2);
                float4 u21 = *reinterpret_cast<const float4*>(p2 + 4);
                float4 u30 = *reinterpret_cast<const float4*>(p3);
                float4 u31 = *reinterpret_cast<const float4*>(p3 + 4);
                a0.x += u00.x; a0.y += u00.y; a0.z += u00.z; a0.w += u00.w;
                a1.x += u01.x; a1.y += u01.y; a1.z += u01.z; a1.w += u01.w;
                a0.x += u10.x; a0.y += u10.y; a0.z += u10.z; a0.w += u10.w;
                a1.x += u11.x; a1.y += u11.y; a1.z += u11.z; a1.w += u11.w;
                a0.x += u20.x; a0.y += u20.y; a0.z += u20.z; a0.w += u20.w;
                a1.x += u21.x; a1.y += u21.y; a1.z += u21.z; a1.w += u21.w;
                a0.x += u30.x; a0.y += u30.y; a0.z += u30.z; a0.w += u30.w;
                a1.x += u31.x; a1.y += u31.y; a1.z += u31.z; a1.w += u31.w;
            }
            for (; e < end; e++) {
                int s = __ldg(&g_colidx[e]);
                const float* p = inh + (size_t)s * HID + cp * 8;
                float4 u0 = *reinterpret_cast<const float4*>(p);
                float4 u1 = *reinterpret_cast<const float4*>(p + 4);
                a0.x += u0.x; a0.y += u0.y; a0.z += u0.z; a0.w += u0.w;
                a1.x += u1.x; a1.y += u1.y; a1.z += u1.z; a1.w += u1.w;
            }
        }
        int q = node >> 2, lo = node & 3;
        float v0[4] = {a0.x, a0.y, a0.z, a0.w};
        float v1[4] = {a1.x, a1.y, a1.z, a1.w};
#pragma unroll
        for (int j = 0; j < 4; j++) {
            int row0 = cp * 8 + j;
            int row1 = cp * 8 + 4 + j;
            asz[row0 * XPAD + SWZ(row0, q) * 4 + lo] = v0[j];
            asz[row1 * XPAD + SWZ(row1, q) * 4 + lo] = v1[j];
        }
    }
    __syncthreads();

    unsigned long long acc[4][4];
#pragma unroll
    for (int i = 0; i < 4; i++)
#pragma unroll
        for (int j = 0; j < 4; j++) acc[i][j] = 0ULL;

    // ---------- GEMM1 (reads W1 from Wsm) ----------
#pragma unroll 8
    for (int kk = 0; kk < 64; kk++) {
        int p0 = SWZ(kk, 2 * ng);
        int p1 = SWZ(kk, 2 * ng + 1);
        float4 xa4 = *reinterpret_cast<const float4*>(&asz[kk * XPAD + p0 * 4]);
        float4 xb4 = *reinterpret_cast<const float4*>(&asz[kk * XPAD + p1 * 4]);
        const ulonglong2* pa = reinterpret_cast<const ulonglong2*>(&xa4);
        const ulonglong2* pb = reinterpret_cast<const ulonglong2*>(&xb4);
        unsigned long long xv[4] = {pa->x, pa->y, pb->x, pb->y};
        float4 wf = *reinterpret_cast<const float4*>(&Wsm[kk * 64 + og * 4]);
        unsigned long long wv[4] = {dup2(wf.x), dup2(wf.y), dup2(wf.z), dup2(wf.w)};
#pragma unroll
        for (int i = 0; i < 4; i++)
#pragma unroll
            for (int j = 0; j < 4; j++) acc[i][j] = ffma2(xv[i], wv[j], acc[i][j]);
    }
    __syncthreads();   // W1 reads and asz reads complete

    // ---------- stage W2 over W1's slab (safe post-sync; ready at next sync) ----
#pragma unroll
    for (int r = 0; r < 4; r++) {
        int i = r * 256 + t;
        reinterpret_cast<float4*>(Wsm)[i] = reinterpret_cast<const float4*>(W2)[i];
    }

    // ---------- epilogue1: BN + relu -> asz (as z) ----------
    {
        float s[4], sh[4];
#pragma unroll
        for (int j = 0; j < 4; j++) {
            int o = og * 4 + j;
            s[j]  = __ldg(g1 + o) * rsqrtf(__ldg(v1 + o) + BN_EPS);
            sh[j] = (__ldg(b1 + o) - __ldg(m1 + o)) * s[j] + __ldg(bb1 + o);
        }
        float f0[4][4], f1[4][4];
#pragma unroll
        for (int i = 0; i < 4; i++)
#pragma unroll
            for (int j = 0; j < 4; j++) unpack2(acc[i][j], f0[i][j], f1[i][j]);
#pragma unroll
        for (int j = 0; j < 4; j++) {
            int row = og * 4 + j;
            float4 A, B;
            A.x = fmaxf(f0[0][j] * s[j] + sh[j], 0.f);
            A.y = fmaxf(f1[0][j] * s[j] + sh[j], 0.f);
            A.z = fmaxf(f0[1][j] * s[j] + sh[j], 0.f);
            A.w = fmaxf(f1[1][j] * s[j] + sh[j], 0.f);
            B.x = fmaxf(f0[2][j] * s[j] + sh[j], 0.f);
            B.y = fmaxf(f1[2][j] * s[j] + sh[j], 0.f);
            B.z = fmaxf(f0[3][j] * s[j] + sh[j], 0.f);
            B.w = fmaxf(f1[3][j] * s[j] + sh[j], 0.f);
            *reinterpret_cast<float4*>(&asz[row * XPAD + SWZ(row, 2 * ng) * 4])     = A;
            *reinterpret_cast<float4*>(&asz[row * XPAD + SWZ(row, 2 * ng + 1) * 4]) = B;
        }
    }
    __syncthreads();   // z ready AND W2 staged

    // ---------- GEMM2 (reads W2 from Wsm) ----------
#pragma unroll
    for (int i = 0; i < 4; i++)
#pragma unroll
        for (int j = 0; j < 4; j++) acc[i][j] = 0ULL;

#pragma unroll 8
    for (int kk = 0; kk < 64; kk++) {
        int p0 = SWZ(kk, 2 * ng);
        int p1 = SWZ(kk, 2 * ng + 1);
        float4 xa4 = *reinterpret_cast<const float4*>(&asz[kk * XPAD + p0 * 4]);
        float4 xb4 = *reinterpret_cast<const float4*>(&asz[kk * XPAD + p1 * 4]);
        const ulonglong2* pa = reinterpret_cast<const ulonglong2*>(&xa4);
        const ulonglong2* pb = reinterpret_cast<const ulonglong2*>(&xb4);
        unsigned long long xv[4] = {pa->x, pa->y, pb->x, pb->y};
        float4 wf = *reinterpret_cast<const float4*>(&Wsm[kk * 64 + og * 4]);
        unsigned long long wv[4] = {dup2(wf.x), dup2(wf.y), dup2(wf.z), dup2(wf.w)};
#pragma unroll
        for (int i = 0; i < 4; i++)
#pragma unroll
            for (int j = 0; j < 4; j++) acc[i][j] = ffma2(xv[i], wv[j], acc[i][j]);
    }

    // ---------- epilogue2: BN + relu -> global h, or pool reduction ----------
    float s[4], sh[4];
#pragma unroll
    for (int j = 0; j < 4; j++) {
        int o = og * 4 + j;
        s[j]  = __ldg(g2 + o) * rsqrtf(__ldg(v2 + o) + BN_EPS);
        sh[j] = (__ldg(b2 + o) - __ldg(m2 + o)) * s[j] + __ldg(bb2 + o);
    }
#pragma unroll
    for (int i = 0; i < 4; i++) {
        float f0[4], f1[4];
#pragma unroll
        for (int j = 0; j < 4; j++) unpack2(acc[i][j], f0[j], f1[j]);
        int node0 = n0 + ng * 8 + 2 * i;
        if (node0 < NN) {
            float4 v;
            v.x = fmaxf(f0[0] * s[0] + sh[0], 0.f);
            v.y = fmaxf(f0[1] * s[1] + sh[1], 0.f);
            v.z = fmaxf(f0[2] * s[2] + sh[2], 0.f);
            v.w = fmaxf(f0[3] * s[3] + sh[3], 0.f);
            if (FINAL) {
                int b = __ldg(batch + node0);
                float4* p = reinterpret_cast<float4*>(g_pool + b * HID + og * 4);
                asm volatile("red.global.add.v4.f32 [%0], {%1,%2,%3,%4};"
                             :: "l"(p), "f"(v.x), "f"(v.y), "f"(v.z), "f"(v.w) : "memory");
            } else {
                *reinterpret_cast<float4*>(outh + (size_t)node0 * HID + og * 4) = v;
            }
        }
        if (node0 + 1 < NN) {
            float4 v;
            v.x = fmaxf(f1[0] * s[0] + sh[0], 0.f);
            v.y = fmaxf(f1[1] * s[1] + sh[1], 0.f);
            v.z = fmaxf(f1[2] * s[2] + sh[2], 0.f);
            v.w = fmaxf(f1[3] * s[3] + sh[3], 0.f);
            if (FINAL) {
                int b = __ldg(batch + node0 + 1);
                float4* p = reinterpret_cast<float4*>(g_pool + b * HID + og * 4);
                asm volatile("red.global.add.v4.f32 [%0], {%1,%2,%3,%4};"
                             :: "l"(p), "f"(v.x), "f"(v.y), "f"(v.z), "f"(v.w) : "memory");
            } else {
                *reinterpret_cast<float4*>(outh + (size_t)(node0 + 1) * HID + og * 4) = v;
            }
        }
    }
}

// ---------------- classifier head ----------------
__global__ void classifier_kernel(const float* __restrict__ W1, const float* __restrict__ b1,
                                  const float* __restrict__ W2, const float* __restrict__ b2,
                                  float* __restrict__ out)
{
    __shared__ float W1s[64 * 32];
    __shared__ float W2s[32 * NCLS];
    __shared__ float b1s[32];
    __shared__ float b2s[NCLS];
    int t = threadIdx.x;
    for (int i = t; i < 64 * 32;   i += 256) W1s[i] = W1[i];
    for (int i = t; i < 32 * NCLS; i += 256) W2s[i] = W2[i];
    if (t < 32)   b1s[t] = b1[t];
    if (t < NCLS) b2s[t] = b2[t];
    __syncthreads();

    int g = blockIdx.x * 256 + t;
    if (g >= GG) return;
    float inv = 1.f / fmaxf((float)g_cnt[g], 1.f);

    float h1[32];
#pragma unroll
    for (int j = 0; j < 32; j++) h1[j] = b1s[j];
    for (int k = 0; k < HID; k++) {
        float p = g_pool[g * HID + k] * inv;
#pragma unroll
        for (int j = 0; j < 32; j++) h1[j] += p * W1s[k * 32 + j];
    }
#pragma unroll
    for (int j = 0; j < 32; j++) h1[j] = fmaxf(h1[j], 0.f);

#pragma unroll
    for (int c = 0; c < NCLS; c++) {
        float o = b2s[c];
#pragma unroll
        for (int j = 0; j < 32; j++) o += h1[j] * W2s[j * NCLS + c];
        out[g * NCLS + c] = o;
    }
}

// ---------------- launcher ----------------
extern "C" void kernel_launch(void* const* d_in, const int* in_sizes, int n_in,
                              void* d_out, int out_size)
{
    const float* x      = (const float*)d_in[0];
    const int*   ei     = (const int*)  d_in[1];
    const int*   batch  = (const int*)  d_in[2];
    const float* emb_w  = (const float*)d_in[3];
    const float* emb_b  = (const float*)d_in[4];
    const float* ibn_g  = (const float*)d_in[5];
    const float* ibn_b  = (const float*)d_in[6];
    const float* ibn_m  = (const float*)d_in[7];
    const float* ibn_v  = (const float*)d_in[8];
    const float* fc1_w  = (const float*)d_in[9];
    const float* fc1_b  = (const float*)d_in[10];
    const float* mbn_g  = (const float*)d_in[11];
    const float* mbn_b  = (const float*)d_in[12];
    const float* mbn_m  = (const float*)d_in[13];
    const float* mbn_v  = (const float*)d_in[14];
    const float* fc2_w  = (const float*)d_in[15];
    const float* fc2_b  = (const float*)d_in[16];
    const float* obn_g  = (const float*)d_in[17];
    const float* obn_b  = (const float*)d_in[18];
    const float* obn_m  = (const float*)d_in[19];
    const float* obn_v  = (const float*)d_in[20];
    const float* cls1_w = (const float*)d_in[21];
    const float* cls1_b = (const float*)d_in[22];
    const float* cls2_w = (const float*)d_in[23];
    const float* cls2_b = (const float*)d_in[24];
    float* out = (float*)d_out;

    const int* src = ei;        // edge_index[0]
    const int* dst = ei + EE;   // edge_index[1]

    float *hA, *hB;
    cudaGetSymbolAddress((void**)&hA, g_hA);
    cudaGetSymbolAddress((void**)&hB, g_hB);

    cudaFuncSetAttribute(fused_mlp<false>, cudaFuncAttributeMaxDynamicSharedMemorySize, MLP_DYN);
    cudaFuncSetAttribute(fused_mlp<true>,  cudaFuncAttributeMaxDynamicSharedMemorySize, MLP_DYN);

    const int NB = (NN + 127) / 128;

    // Side stream forked off the capture line via events.
    cudaStream_t s2;
    cudaEvent_t evF, evJ;
    cudaStreamCreateWithFlags(&s2, cudaStreamNonBlocking);
    cudaEventCreateWithFlags(&evF, cudaEventDisableTiming);
    cudaEventCreateWithFlags(&evJ, cudaEventDisableTiming);

    cudaEventRecord(evF, 0);
    cudaStreamWaitEvent(s2, evF, 0);

    // ---- side stream: CSR build + pool/cnt init (independent of embed) ----
    csr_zero_kernel <<<(NN + 255) / 256, 256, 0, s2>>>();
    csr_hist_kernel <<<(EE + 255) / 256, 256, 0, s2>>>(dst);
    csr_scan1_kernel<<<NBLK, 256, 0, s2>>>();
    csr_scan2_kernel<<<1, 256, 0, s2>>>();
    csr_scan3_kernel<<<(NN + 255) / 256, 256, 0, s2>>>();
    csr_fill_kernel <<<(EE + 255) / 256, 256, 0, s2>>>(src, dst);
    zero_pool_kernel<<<(GG * HID + 255) / 256, 256, 0, s2>>>();
    cnt_hist_kernel <<<(NN + 255) / 256, 256, 0, s2>>>(batch);
    cudaEventRecord(evJ, s2);

    // ---- main stream: embed runs concurrently with the side branch ----
    embed_kernel<<<NB, 256>>>(x, emb_w, emb_b, ibn_g, ibn_b, ibn_m, ibn_v, hA);

    cudaStreamWaitEvent(0, evJ, 0);   // join: CSR + pool init done

    // ping-pong layers; final layer reduces straight into g_pool
    float* bufs[2] = {hA, hB};
    for (int l = 0; l < LAYERS; l++) {
        const float* inp  = bufs[l & 1];
        float*       outp = bufs[(l + 1) & 1];
        if (l < LAYERS - 1) {
            fused_mlp<false><<<NB, 256, MLP_DYN>>>(
                inp,
                fc1_w + (size_t)l * HID * HID, fc1_b + l * HID,
                mbn_g + l * HID, mbn_b + l * HID, mbn_m + l * HID, mbn_v + l * HID,
                fc2_w + (size_t)l * HID * HID, fc2_b + l * HID,
                obn_g + l * HID, obn_b + l * HID, obn_m + l * HID, obn_v + l * HID,
                outp, batch);
        } else {
            fused_mlp<true><<<NB, 256, MLP_DYN>>>(
                inp,
                fc1_w + (size_t)l * HID * HID, fc1_b + l * HID,
                mbn_g + l * HID, mbn_b + l * HID, mbn_m + l * HID, mbn_v + l * HID,
                fc2_w + (size_t)l * HID * HID, fc2_b + l * HID,
                obn_g + l * HID, obn_b + l * HID, obn_m + l * HID, obn_v + l * HID,
                outp, batch);
        }
    }

    classifier_kernel<<<(GG + 255) / 256, 256>>>(cls1_w, cls1_b, cls2_w, cls2_b, out);
}